// round 2
// baseline (speedup 1.0000x reference)
#include <cuda_runtime.h>
#include <cuda_bf16.h>
#include <cstdint>

// Problem constants
#define M_TOTAL 8192   // B*S = 4*2048
#define K_TOTAL 4096   // IN_F
#define N_TOTAL 4096   // OUT_F

// GEMM tiling
#define BM 128
#define BN 128
#define BK 64
#define LDT 80         // padded shared row pitch (bytes) -> conflict-free
#define KT (K_TOTAL / BK)

// ---------------- device scratch (no runtime allocation allowed) ------------
__device__ unsigned int g_amax_bits;
__device__ int8_t g_xq[(size_t)M_TOTAL * K_TOTAL];
__device__ int8_t g_wq[(size_t)N_TOTAL * K_TOTAL];

// ---------------- kernel 0: reset amax --------------------------------------
__global__ void reset_kernel() { g_amax_bits = 0u; }

// ---------------- kernel 1: global abs-max over x ---------------------------
__global__ void amax_kernel(const float* __restrict__ x, int n4) {
    const float4* x4 = (const float4*)x;
    float m = 0.f;
    for (int i = blockIdx.x * blockDim.x + threadIdx.x; i < n4;
         i += gridDim.x * blockDim.x) {
        float4 v = x4[i];
        m = fmaxf(m, fmaxf(fmaxf(fabsf(v.x), fabsf(v.y)),
                           fmaxf(fabsf(v.z), fabsf(v.w))));
    }
    #pragma unroll
    for (int o = 16; o; o >>= 1) m = fmaxf(m, __shfl_xor_sync(0xffffffffu, m, o));
    __shared__ float s[32];
    int lane = threadIdx.x & 31, w = threadIdx.x >> 5;
    if (lane == 0) s[w] = m;
    __syncthreads();
    if (w == 0) {
        m = (lane < (int)(blockDim.x >> 5)) ? s[lane] : 0.f;
        #pragma unroll
        for (int o = 16; o; o >>= 1) m = fmaxf(m, __shfl_xor_sync(0xffffffffu, m, o));
        if (lane == 0) atomicMax(&g_amax_bits, __float_as_uint(m));
    }
}

// ---------------- kernel 2: quantize x -> int8 ------------------------------
__global__ void quant_kernel(const float* __restrict__ x, int n4) {
    float amax = __uint_as_float(g_amax_bits);
    float scale = (amax == 0.f) ? 1.f : __fdiv_rn(amax, 127.f);
    const float4* x4 = (const float4*)x;
    char4* q4 = (char4*)g_xq;
    for (int i = blockIdx.x * blockDim.x + threadIdx.x; i < n4;
         i += gridDim.x * blockDim.x) {
        float4 v = x4[i];
        int a = __float2int_rn(__fdiv_rn(v.x, scale));
        int b = __float2int_rn(__fdiv_rn(v.y, scale));
        int c = __float2int_rn(__fdiv_rn(v.z, scale));
        int d = __float2int_rn(__fdiv_rn(v.w, scale));
        a = max(-127, min(127, a));
        b = max(-127, min(127, b));
        c = max(-127, min(127, c));
        d = max(-127, min(127, d));
        char4 q;
        q.x = (char)a; q.y = (char)b; q.z = (char)c; q.w = (char)d;
        q4[i] = q;
    }
}

// ---------------- kernel 2b: pack w (delivered as int32) -> int8 ------------
__global__ void packw_kernel(const int* __restrict__ w32, int n4) {
    const int4* w4 = (const int4*)w32;
    char4* q4 = (char4*)g_wq;
    for (int i = blockIdx.x * blockDim.x + threadIdx.x; i < n4;
         i += gridDim.x * blockDim.x) {
        int4 v = w4[i];
        char4 q;
        q.x = (char)v.x; q.y = (char)v.y; q.z = (char)v.z; q.w = (char)v.w;
        q4[i] = q;
    }
}

// ---------------- int8 mma helper -------------------------------------------
__device__ __forceinline__ void mma_s8(int* c, const uint32_t* a, const uint32_t* b) {
    asm volatile(
        "mma.sync.aligned.m16n8k32.row.col.s32.s8.s8.s32 "
        "{%0,%1,%2,%3}, {%4,%5,%6,%7}, {%8,%9}, {%0,%1,%2,%3};"
        : "+r"(c[0]), "+r"(c[1]), "+r"(c[2]), "+r"(c[3])
        : "r"(a[0]), "r"(a[1]), "r"(a[2]), "r"(a[3]), "r"(b[0]), "r"(b[1]));
}

__device__ __forceinline__ void cp_async16(void* smem_dst, const void* gsrc) {
    uint32_t d = (uint32_t)__cvta_generic_to_shared(smem_dst);
    asm volatile("cp.async.cg.shared.global [%0], [%1], 16;\n"
                 :: "r"(d), "l"(gsrc) : "memory");
}

// epilogue: replicate bf16(bf16(i32) * bf16(scale)) exactly
__device__ __forceinline__ float dequant_one(int acc, float csf) {
    float v = __bfloat162float(__float2bfloat16((float)acc));
    return __bfloat162float(__float2bfloat16(v * csf));
}

// ---------------- kernel 3: int8 GEMM + dequant epilogue --------------------
__global__ __launch_bounds__(256, 2)
void gemm_kernel(const float* __restrict__ w_scale_p,
                 const float* __restrict__ bias,
                 float* __restrict__ out) {
    __shared__ int8_t Ash[2][BM * LDT];
    __shared__ int8_t Bsh[2][BN * LDT];

    const int tid = threadIdx.x;
    const int bm = blockIdx.y, bn = blockIdx.x;
    const int8_t* Ag = g_xq + (size_t)bm * BM * K_TOTAL;
    const int8_t* Bg = g_wq + (size_t)bn * BN * K_TOTAL;

    const int lane = tid & 31;
    const int wid = tid >> 5;
    const int wm = (wid >> 2) * 64;  // 0 or 64
    const int wn = (wid & 3) * 32;   // 0,32,64,96

    int acc[4][4][4];
    #pragma unroll
    for (int mt = 0; mt < 4; ++mt)
        #pragma unroll
        for (int nt = 0; nt < 4; ++nt)
            #pragma unroll
            for (int i = 0; i < 4; ++i) acc[mt][nt][i] = 0;

    auto load_tile = [&](int kt, int buf) {
        int koff = kt * BK;
        #pragma unroll
        for (int it = 0; it < 2; ++it) {
            int idx = tid + it * 256;   // 0..511
            int row = idx >> 2;
            int c = (idx & 3) * 16;
            cp_async16(&Ash[buf][row * LDT + c],
                       Ag + (size_t)row * K_TOTAL + koff + c);
            cp_async16(&Bsh[buf][row * LDT + c],
                       Bg + (size_t)row * K_TOTAL + koff + c);
        }
    };

    load_tile(0, 0);
    asm volatile("cp.async.commit_group;\n" ::: "memory");
    load_tile(1, 1);
    asm volatile("cp.async.commit_group;\n" ::: "memory");

    for (int kt = 0; kt < KT; ++kt) {
        if (kt < KT - 1)
            asm volatile("cp.async.wait_group 1;\n" ::: "memory");
        else
            asm volatile("cp.async.wait_group 0;\n" ::: "memory");
        __syncthreads();

        const int buf = kt & 1;
        #pragma unroll
        for (int ks = 0; ks < 2; ++ks) {
            const int kb = ks * 32 + (lane & 3) * 4;
            uint32_t afr[4][4];
            #pragma unroll
            for (int mt = 0; mt < 4; ++mt) {
                const int8_t* base = &Ash[buf][(wm + mt * 16 + (lane >> 2)) * LDT + kb];
                afr[mt][0] = *(const uint32_t*)(base);
                afr[mt][1] = *(const uint32_t*)(base + 8 * LDT);
                afr[mt][2] = *(const uint32_t*)(base + 16);
                afr[mt][3] = *(const uint32_t*)(base + 8 * LDT + 16);
            }
            uint32_t bfr[4][2];
            #pragma unroll
            for (int nt = 0; nt < 4; ++nt) {
                const int8_t* base = &Bsh[buf][(wn + nt * 8 + (lane >> 2)) * LDT + kb];
                bfr[nt][0] = *(const uint32_t*)(base);
                bfr[nt][1] = *(const uint32_t*)(base + 16);
            }
            #pragma unroll
            for (int mt = 0; mt < 4; ++mt)
                #pragma unroll
                for (int nt = 0; nt < 4; ++nt)
                    mma_s8(acc[mt][nt], afr[mt], bfr[nt]);
        }
        __syncthreads();

        if (kt + 2 < KT) {
            load_tile(kt + 2, buf);
            asm volatile("cp.async.commit_group;\n" ::: "memory");
        }
    }

    // ---- epilogue ----
    float amax = __uint_as_float(g_amax_bits);
    float xs = (amax == 0.f) ? 1.f : __fdiv_rn(amax, 127.f);
    float csf = __bfloat162float(__float2bfloat16(xs * w_scale_p[0]));

    #pragma unroll
    for (int mt = 0; mt < 4; ++mt) {
        #pragma unroll
        for (int nt = 0; nt < 4; ++nt) {
            int m0 = bm * BM + wm + mt * 16 + (lane >> 2);
            int n0 = bn * BN + wn + nt * 8 + (lane & 3) * 2;
            float b0 = bias[n0];
            float b1 = bias[n0 + 1];
            float2 r0, r1;
            r0.x = dequant_one(acc[mt][nt][0], csf) + b0;
            r0.y = dequant_one(acc[mt][nt][1], csf) + b1;
            r1.x = dequant_one(acc[mt][nt][2], csf) + b0;
            r1.y = dequant_one(acc[mt][nt][3], csf) + b1;
            *(float2*)&out[(size_t)m0 * N_TOTAL + n0] = r0;
            *(float2*)&out[(size_t)(m0 + 8) * N_TOTAL + n0] = r1;
        }
    }
}

// ---------------- launcher ---------------------------------------------------
extern "C" void kernel_launch(void* const* d_in, const int* in_sizes, int n_in,
                              void* d_out, int out_size) {
    const float* x = (const float*)d_in[0];          // [4,2048,4096] fp32
    const int* w32 = (const int*)d_in[1];            // [4096,4096] int8 delivered as int32
    const float* wscale = (const float*)d_in[2];     // scalar fp32
    const float* bias = (const float*)d_in[3];       // [4096] fp32
    float* out = (float*)d_out;                      // [4,2048,4096] fp32

    const int n4x = (M_TOTAL * K_TOTAL) / 4;
    const int n4w = (N_TOTAL * K_TOTAL) / 4;

    reset_kernel<<<1, 1>>>();
    amax_kernel<<<592, 256>>>(x, n4x);
    quant_kernel<<<592, 256>>>(x, n4x);
    packw_kernel<<<592, 256>>>(w32, n4w);

    dim3 grid(N_TOTAL / BN, M_TOTAL / BM);
    gemm_kernel<<<grid, 256>>>(wscale, bias, out);
}